// round 10
// baseline (speedup 1.0000x reference)
#include <cuda_runtime.h>
#include <cuda_bf16.h>
#include <cstdint>

#define BATCH 4
#define CH    512
#define NPIX  4096
#define MID   64

// ---------------- global scratch ----------------
// Fragment-packed operands: one uint4 per lane per fragment (LDG.128 in attn).
__device__ uint4 g_Qf[BATCH * 256 * 4 * 32];        // (b, qb16, ks4, lane)  A-frag
__device__ uint4 g_Kf[BATCH * 256 * 4 * 32];        // (b, jb16, ks4, lane)  B-frag
__device__ uint4 g_Vf[BATCH * 32 * 256 * 32];       // (b, db16, kb16, lane) B-frag
__device__ __nv_bfloat16 g_xb[BATCH * CH * NPIX];   // bf16 copy of x
__device__ __nv_bfloat16 g_Wb[640 * CH];            // rows: 0-63 Wq, 64-127 Wk, 128-639 Wv
__device__ float         g_bias[640];

// ---------------- mma.sync helpers ----------------
__device__ __forceinline__ uint32_t smem_u32(const void* p) {
    uint32_t a;
    asm("{ .reg .u64 t; cvta.to.shared.u64 t, %1; cvt.u32.u64 %0, t; }" : "=r"(a) : "l"(p));
    return a;
}
__device__ __forceinline__ void ldm_x4(uint32_t r[4], uint32_t addr) {
    asm volatile("ldmatrix.sync.aligned.m8n8.x4.shared.b16 {%0,%1,%2,%3}, [%4];"
                 : "=r"(r[0]), "=r"(r[1]), "=r"(r[2]), "=r"(r[3]) : "r"(addr));
}
__device__ __forceinline__ void ldm_x4t(uint32_t r[4], uint32_t addr) {
    asm volatile("ldmatrix.sync.aligned.m8n8.x4.trans.shared.b16 {%0,%1,%2,%3}, [%4];"
                 : "=r"(r[0]), "=r"(r[1]), "=r"(r[2]), "=r"(r[3]) : "r"(addr));
}
__device__ __forceinline__ void mma16816(float* c, const uint32_t* a, uint32_t b0, uint32_t b1) {
    asm volatile("mma.sync.aligned.m16n8k16.row.col.f32.bf16.bf16.f32 "
                 "{%0,%1,%2,%3}, {%4,%5,%6,%7}, {%8,%9}, {%0,%1,%2,%3};"
                 : "+f"(c[0]), "+f"(c[1]), "+f"(c[2]), "+f"(c[3])
                 : "r"(a[0]), "r"(a[1]), "r"(a[2]), "r"(a[3]), "r"(b0), "r"(b1));
}
__device__ __forceinline__ uint32_t bpack(float a, float b) {
    __nv_bfloat162 h = __floats2bfloat162_rn(a, b);
    return *(uint32_t*)&h;
}

// =================================================================
// Kernel 0a: convert x -> bf16 (8 elems / thread)
// =================================================================
__global__ __launch_bounds__(256) void conv_x_kernel(const float* __restrict__ x)
{
    size_t i = ((size_t)blockIdx.x * 256 + threadIdx.x) * 8;
    float4 a = *(const float4*)&x[i];
    float4 c = *(const float4*)&x[i + 4];
    *(uint4*)&g_xb[i] = make_uint4(bpack(a.x, a.y), bpack(a.z, a.w),
                                   bpack(c.x, c.y), bpack(c.z, c.w));
}

// =================================================================
// Kernel 0b: pack W -> g_Wb (bf16) + g_bias
// =================================================================
__global__ __launch_bounds__(256) void conv_w_kernel(
    const float* __restrict__ Wq, const float* __restrict__ bq,
    const float* __restrict__ Wk, const float* __restrict__ bk,
    const float* __restrict__ Wv, const float* __restrict__ bv)
{
    int gid = blockIdx.x * 256 + threadIdx.x;
    size_t base = (size_t)gid * 8;
    int row = (int)(base >> 9), k = (int)(base & 511);
    const float* src;
    if (row < 64)       src = Wq + row * CH + k;
    else if (row < 128) src = Wk + (row - 64) * CH + k;
    else                src = Wv + (row - 128) * CH + k;
    float4 a = *(const float4*)src;
    float4 c = *(const float4*)(src + 4);
    *(uint4*)&g_Wb[base] = make_uint4(bpack(a.x, a.y), bpack(a.z, a.w),
                                      bpack(c.x, c.y), bpack(c.z, c.w));
    if (gid < 640)
        g_bias[gid] = (gid < 64) ? bq[gid] : (gid < 128) ? bk[gid - 64] : bv[gid - 128];
}

// =================================================================
// Kernel 1: QKV projection (bf16 mma.sync GEMM), epilogue writes
// fragment-packed Q/K/V directly.
// =================================================================
#define PW_STR 144
#define PX_STR 272

__global__ __launch_bounds__(256) void proj_mma_kernel()
{
    __shared__ __align__(16) char ps[9216 + 17408];
    char* Wt = ps;
    char* Xt = ps + 9216;
    const uint32_t smb = smem_u32(ps);
    const int tid = threadIdx.x, lane = tid & 31, wid = tid >> 5;
    const int mg = wid >> 1, nh = wid & 1;
    const int n0 = blockIdx.x * 128;
    const int rg = blockIdx.y;          // 0=Q rows, 1=K rows, 2-9=V rows
    const int b  = blockIdx.z;

    float fc[8][4];
#pragma unroll
    for (int nb = 0; nb < 8; nb++)
#pragma unroll
        for (int e = 0; e < 4; e++) fc[nb][e] = 0.f;

    const uint32_t aoffA  = (lane & 15) * PW_STR + (lane >> 4) * 16;
    const uint32_t aoffBT = ((lane & 7) + ((lane >> 3) & 1) * 8) * PX_STR + (lane >> 4) * 16;

    for (int kc = 0; kc < CH; kc += 64) {
        __syncthreads();
        for (int idx = tid; idx < 512; idx += 256) {
            int row = idx >> 3, c16 = idx & 7;
            *(uint4*)(Wt + row * PW_STR + c16 * 16) =
                *(const uint4*)&g_Wb[(size_t)(rg * 64 + row) * CH + kc + c16 * 8];
        }
        for (int idx = tid; idx < 1024; idx += 256) {
            int row = idx >> 4, c16 = idx & 15;
            *(uint4*)(Xt + row * PX_STR + c16 * 16) =
                *(const uint4*)&g_xb[((size_t)b * CH + kc + row) * NPIX + n0 + c16 * 8];
        }
        __syncthreads();
#pragma unroll
        for (int ks = 0; ks < 4; ks++) {
            uint32_t aW[4];
            ldm_x4(aW, smb + (mg * 16) * PW_STR + ks * 32 + aoffA);
#pragma unroll
            for (int nb = 0; nb < 4; nb++) {
                uint32_t bx[4];
                ldm_x4t(bx, smb + 9216 + (ks * 16) * PX_STR + (nh * 64 + nb * 16) * 2 + aoffBT);
                mma16816(fc[2 * nb],     aW, bx[0], bx[1]);
                mma16816(fc[2 * nb + 1], aW, bx[2], bx[3]);
            }
        }
    }

    const int mr = mg * 16 + (lane >> 2);
    const float b0 = g_bias[rg * 64 + mr], b1 = g_bias[rg * 64 + mr + 8];

    if (rg >= 2) {
        // V fragment-packed store: frag = (db16 = (rg-2)*4+mg, kb16 = n0/16 + nh*4 + jg)
        // lane uint4 = { (d-lo, j k0-7), (d-lo, j k8-15), (d-hi, k0-7), (d-hi, k8-15) }
        const int db = (rg - 2) * 4 + mg;
#pragma unroll
        for (int jg = 0; jg < 4; jg++) {
            int nb0 = 2 * jg, nb1 = 2 * jg + 1;
            uint4 v;
            v.x = bpack(fc[nb0][0] + b0, fc[nb0][1] + b0);
            v.y = bpack(fc[nb1][0] + b0, fc[nb1][1] + b0);
            v.z = bpack(fc[nb0][2] + b1, fc[nb0][3] + b1);
            v.w = bpack(fc[nb1][2] + b1, fc[nb1][3] + b1);
            int kb = blockIdx.x * 8 + nh * 4 + jg;
            g_Vf[(((size_t)b * 32 + db) * 256 + kb) * 32 + lane] = v;
        }
    } else {
        // Q/K: transpose through smem staging st[128 n][72 m], then gather frags
        __syncthreads();
        __nv_bfloat16* st = (__nv_bfloat16*)ps;
#pragma unroll
        for (int nb = 0; nb < 8; nb++) {
            int nl = nh * 64 + nb * 8 + (lane & 3) * 2;
            st[nl * 72 + mr]           = __float2bfloat16(fc[nb][0] + b0);
            st[(nl + 1) * 72 + mr]     = __float2bfloat16(fc[nb][1] + b0);
            st[nl * 72 + mr + 8]       = __float2bfloat16(fc[nb][2] + b1);
            st[(nl + 1) * 72 + mr + 8] = __float2bfloat16(fc[nb][3] + b1);
        }
        __syncthreads();
        // warp wid owns token-block (n0/16 + wid); ks = 0..3 m-blocks
        const int jl = wid * 16 + (lane >> 2);
        const int gb = blockIdx.x * 8 + wid;
#pragma unroll
        for (int ks = 0; ks < 4; ks++) {
            int m = ks * 16 + 2 * (lane & 3);
            uint32_t q00 = *(uint32_t*)&st[jl * 72 + m];
            uint32_t q01 = *(uint32_t*)&st[jl * 72 + m + 8];
            uint32_t q10 = *(uint32_t*)&st[(jl + 8) * 72 + m];
            uint32_t q11 = *(uint32_t*)&st[(jl + 8) * 72 + m + 8];
            size_t fi = (((size_t)b * 256 + gb) * 4 + ks) * 32 + lane;
            if (rg == 0)  // A-frag order: {(q,m),(q+8,m),(q,m+8),(q+8,m+8)}
                g_Qf[fi] = make_uint4(q00, q10, q01, q11);
            else          // B-frag order: {(j,m),(j,m+8),(j+8,m),(j+8,m+8)}
                g_Kf[fi] = make_uint4(q00, q01, q10, q11);
        }
    }
}

// =================================================================
// Kernel 2: flash attention, all operands fragment-packed in gmem.
// CTA = (128 q, 128 d, batch), 8 warps = 8 q-groups of 16.
// No shared memory, no syncs; P built in registers from scores.
// =================================================================
__global__ __launch_bounds__(256, 2) void attn_mma(
    const float* __restrict__ x, const float* __restrict__ gamma,
    float* __restrict__ out)
{
    const int tid  = threadIdx.x;
    const int lane = tid & 31, wid = tid >> 5;
    const int b   = blockIdx.z;
    const int db0 = blockIdx.y * 8;            // d block16 base (d0 = 128*by)
    const int qb  = blockIdx.x * 8 + wid;      // q block16 index

    // persistent Q A-fragments (16 regs)
    uint4 q4[4];
#pragma unroll
    for (int ks = 0; ks < 4; ks++)
        q4[ks] = g_Qf[(((size_t)b * 256 + qb) * 4 + ks) * 32 + lane];

    float facc[16][4];
#pragma unroll
    for (int nb = 0; nb < 16; nb++)
#pragma unroll
        for (int e = 0; e < 4; e++) facc[nb][e] = 0.f;
    float lr0 = 0.f, lr1 = 0.f;

    const uint4* Kf = &g_Kf[((size_t)b * 256) * 4 * 32];
    const uint4* Vf = &g_Vf[((size_t)b * 32 + db0) * 256 * 32];

    for (int jt = 0; jt < 64; jt++) {
        // ---- scores: S[16q x 64j] ----
        float sacc[8][4];
#pragma unroll
        for (int nb = 0; nb < 8; nb++)
#pragma unroll
            for (int e = 0; e < 4; e++) sacc[nb][e] = 0.f;

#pragma unroll
        for (int ks = 0; ks < 4; ks++)
#pragma unroll
            for (int jbi = 0; jbi < 4; jbi++) {
                uint4 kf = Kf[((size_t)(jt * 4 + jbi) * 4 + ks) * 32 + lane];
                mma16816(sacc[2 * jbi],     (const uint32_t*)&q4[ks], kf.x, kf.y);
                mma16816(sacc[2 * jbi + 1], (const uint32_t*)&q4[ks], kf.z, kf.w);
            }

        // ---- exp + build P A-fragments in registers ----
        uint32_t pf[4][4];
#pragma unroll
        for (int kk = 0; kk < 4; kk++) {
            int nbo = 2 * kk;
            float e0 = __expf(sacc[nbo][0]),     e1 = __expf(sacc[nbo][1]);
            float e2 = __expf(sacc[nbo][2]),     e3 = __expf(sacc[nbo][3]);
            float f0 = __expf(sacc[nbo + 1][0]), f1 = __expf(sacc[nbo + 1][1]);
            float f2 = __expf(sacc[nbo + 1][2]), f3 = __expf(sacc[nbo + 1][3]);
            lr0 += (e0 + e1) + (f0 + f1);
            lr1 += (e2 + e3) + (f2 + f3);
            pf[kk][0] = bpack(e0, e1);   // (q,   j-lo)
            pf[kk][1] = bpack(e2, e3);   // (q+8, j-lo)
            pf[kk][2] = bpack(f0, f1);   // (q,   j-hi)
            pf[kk][3] = bpack(f2, f3);   // (q+8, j-hi)
        }

        // ---- PV: feat[16q x 128d] += P * V ----
#pragma unroll
        for (int ks = 0; ks < 4; ks++)
#pragma unroll
            for (int nb2 = 0; nb2 < 8; nb2++) {
                uint4 vf = Vf[((size_t)nb2 * 256 + jt * 4 + ks) * 32 + lane];
                mma16816(facc[2 * nb2],     pf[ks], vf.x, vf.y);
                mma16816(facc[2 * nb2 + 1], pf[ks], vf.z, vf.w);
            }
    }

    // ---- row-sum reduce over the 4 lanes of each row group ----
    lr0 += __shfl_xor_sync(0xffffffffu, lr0, 1);
    lr0 += __shfl_xor_sync(0xffffffffu, lr0, 2);
    lr1 += __shfl_xor_sync(0xffffffffu, lr1, 1);
    lr1 += __shfl_xor_sync(0xffffffffu, lr1, 2);

    const float g = gamma[0];
    const float sc0 = g / lr0, sc1 = g / lr1;
    const int q0 = blockIdx.x * 128 + wid * 16 + (lane >> 2);
    const int d0 = blockIdx.y * 128;

#pragma unroll
    for (int nb = 0; nb < 16; nb++) {
        int d = d0 + nb * 8 + 2 * (lane & 3);
        size_t ga = (size_t)(b * CH + d) * NPIX + q0;
        out[ga]            = facc[nb][0] * sc0 + x[ga];
        out[ga + NPIX]     = facc[nb][1] * sc0 + x[ga + NPIX];
        out[ga + 8]        = facc[nb][2] * sc1 + x[ga + 8];
        out[ga + NPIX + 8] = facc[nb][3] * sc1 + x[ga + NPIX + 8];
    }
}

// =================================================================
extern "C" void kernel_launch(void* const* d_in, const int* in_sizes, int n_in,
                              void* d_out, int out_size)
{
    const float* x     = (const float*)d_in[0];
    const float* Wq    = (const float*)d_in[1];
    const float* bq    = (const float*)d_in[2];
    const float* Wk    = (const float*)d_in[3];
    const float* bk    = (const float*)d_in[4];
    const float* Wv    = (const float*)d_in[5];
    const float* bv    = (const float*)d_in[6];
    const float* gamma = (const float*)d_in[7];
    float* out = (float*)d_out;

    conv_x_kernel<<<(BATCH * CH * NPIX) / (256 * 8), 256>>>(x);
    conv_w_kernel<<<160, 256>>>(Wq, bq, Wk, bk, Wv, bv);
    proj_mma_kernel<<<dim3(NPIX / 128, 10, BATCH), 256>>>();
    attn_mma<<<dim3(NPIX / 128, 4, BATCH), 256>>>(x, gamma, out);
}

// round 11
// speedup vs baseline: 1.9562x; 1.9562x over previous
#include <cuda_runtime.h>
#include <cuda_bf16.h>
#include <cstdint>

#define BATCH 4
#define CH    512
#define NPIX  4096
#define MID   64

// ---------------- global scratch ----------------
// Fragment-packed operands: one uint4 per lane per fragment.
__device__ uint4 g_Qf[BATCH * 256 * 4 * 32];        // (b, qb16, ks4, lane)  A-frag
__device__ uint4 g_Kf[BATCH * 256 * 4 * 32];        // (b, jb16, ks4, lane)  B-frag
__device__ uint4 g_Vf[BATCH * 32 * 256 * 32];       // (b, db16, kb16, lane) B-frag
__device__ __nv_bfloat16 g_xb[BATCH * CH * NPIX];   // bf16 copy of x
__device__ __nv_bfloat16 g_Wb[640 * CH];            // rows: 0-63 Wq, 64-127 Wk, 128-639 Wv
__device__ float         g_bias[640];

// ---------------- helpers ----------------
__device__ __forceinline__ uint32_t smem_u32(const void* p) {
    uint32_t a;
    asm("{ .reg .u64 t; cvta.to.shared.u64 t, %1; cvt.u32.u64 %0, t; }" : "=r"(a) : "l"(p));
    return a;
}
__device__ __forceinline__ void ldm_x4(uint32_t r[4], uint32_t addr) {
    asm volatile("ldmatrix.sync.aligned.m8n8.x4.shared.b16 {%0,%1,%2,%3}, [%4];"
                 : "=r"(r[0]), "=r"(r[1]), "=r"(r[2]), "=r"(r[3]) : "r"(addr));
}
__device__ __forceinline__ void ldm_x4t(uint32_t r[4], uint32_t addr) {
    asm volatile("ldmatrix.sync.aligned.m8n8.x4.trans.shared.b16 {%0,%1,%2,%3}, [%4];"
                 : "=r"(r[0]), "=r"(r[1]), "=r"(r[2]), "=r"(r[3]) : "r"(addr));
}
__device__ __forceinline__ void mma16816(float* c, const uint32_t* a, uint32_t b0, uint32_t b1) {
    asm volatile("mma.sync.aligned.m16n8k16.row.col.f32.bf16.bf16.f32 "
                 "{%0,%1,%2,%3}, {%4,%5,%6,%7}, {%8,%9}, {%0,%1,%2,%3};"
                 : "+f"(c[0]), "+f"(c[1]), "+f"(c[2]), "+f"(c[3])
                 : "r"(a[0]), "r"(a[1]), "r"(a[2]), "r"(a[3]), "r"(b0), "r"(b1));
}
__device__ __forceinline__ uint32_t bpack(float a, float b) {
    __nv_bfloat162 h = __floats2bfloat162_rn(a, b);
    return *(uint32_t*)&h;
}
__device__ __forceinline__ void cp16(uint32_t dst, const void* src) {
    asm volatile("cp.async.cg.shared.global [%0], [%1], 16;" :: "r"(dst), "l"(src));
}
#define CP_COMMIT() asm volatile("cp.async.commit_group;" ::: "memory")
#define CP_WAIT1()  asm volatile("cp.async.wait_group 1;" ::: "memory")

// =================================================================
// Kernel 0a: convert x -> bf16 (8 elems / thread)
// =================================================================
__global__ __launch_bounds__(256) void conv_x_kernel(const float* __restrict__ x)
{
    size_t i = ((size_t)blockIdx.x * 256 + threadIdx.x) * 8;
    float4 a = *(const float4*)&x[i];
    float4 c = *(const float4*)&x[i + 4];
    *(uint4*)&g_xb[i] = make_uint4(bpack(a.x, a.y), bpack(a.z, a.w),
                                   bpack(c.x, c.y), bpack(c.z, c.w));
}

// =================================================================
// Kernel 0b: pack W -> g_Wb (bf16) + g_bias
// =================================================================
__global__ __launch_bounds__(256) void conv_w_kernel(
    const float* __restrict__ Wq, const float* __restrict__ bq,
    const float* __restrict__ Wk, const float* __restrict__ bk,
    const float* __restrict__ Wv, const float* __restrict__ bv)
{
    int gid = blockIdx.x * 256 + threadIdx.x;
    size_t base = (size_t)gid * 8;
    int row = (int)(base >> 9), k = (int)(base & 511);
    const float* src;
    if (row < 64)       src = Wq + row * CH + k;
    else if (row < 128) src = Wk + (row - 64) * CH + k;
    else                src = Wv + (row - 128) * CH + k;
    float4 a = *(const float4*)src;
    float4 c = *(const float4*)(src + 4);
    *(uint4*)&g_Wb[base] = make_uint4(bpack(a.x, a.y), bpack(a.z, a.w),
                                      bpack(c.x, c.y), bpack(c.z, c.w));
    if (gid < 640)
        g_bias[gid] = (gid < 64) ? bq[gid] : (gid < 128) ? bk[gid - 64] : bv[gid - 128];
}

// =================================================================
// Kernel 1: QKV projection (bf16 mma.sync GEMM), epilogue writes
// fragment-packed Q/K/V directly.  (unchanged from R10 — verified)
// =================================================================
#define PW_STR 144
#define PX_STR 272

__global__ __launch_bounds__(256) void proj_mma_kernel()
{
    __shared__ __align__(16) char ps[9216 + 17408];
    char* Wt = ps;
    char* Xt = ps + 9216;
    const uint32_t smb = smem_u32(ps);
    const int tid = threadIdx.x, lane = tid & 31, wid = tid >> 5;
    const int mg = wid >> 1, nh = wid & 1;
    const int n0 = blockIdx.x * 128;
    const int rg = blockIdx.y;          // 0=Q rows, 1=K rows, 2-9=V rows
    const int b  = blockIdx.z;

    float fc[8][4];
#pragma unroll
    for (int nb = 0; nb < 8; nb++)
#pragma unroll
        for (int e = 0; e < 4; e++) fc[nb][e] = 0.f;

    const uint32_t aoffA  = (lane & 15) * PW_STR + (lane >> 4) * 16;
    const uint32_t aoffBT = ((lane & 7) + ((lane >> 3) & 1) * 8) * PX_STR + (lane >> 4) * 16;

    for (int kc = 0; kc < CH; kc += 64) {
        __syncthreads();
        for (int idx = tid; idx < 512; idx += 256) {
            int row = idx >> 3, c16 = idx & 7;
            *(uint4*)(Wt + row * PW_STR + c16 * 16) =
                *(const uint4*)&g_Wb[(size_t)(rg * 64 + row) * CH + kc + c16 * 8];
        }
        for (int idx = tid; idx < 1024; idx += 256) {
            int row = idx >> 4, c16 = idx & 15;
            *(uint4*)(Xt + row * PX_STR + c16 * 16) =
                *(const uint4*)&g_xb[((size_t)b * CH + kc + row) * NPIX + n0 + c16 * 8];
        }
        __syncthreads();
#pragma unroll
        for (int ks = 0; ks < 4; ks++) {
            uint32_t aW[4];
            ldm_x4(aW, smb + (mg * 16) * PW_STR + ks * 32 + aoffA);
#pragma unroll
            for (int nb = 0; nb < 4; nb++) {
                uint32_t bx[4];
                ldm_x4t(bx, smb + 9216 + (ks * 16) * PX_STR + (nh * 64 + nb * 16) * 2 + aoffBT);
                mma16816(fc[2 * nb],     aW, bx[0], bx[1]);
                mma16816(fc[2 * nb + 1], aW, bx[2], bx[3]);
            }
        }
    }

    const int mr = mg * 16 + (lane >> 2);
    const float b0 = g_bias[rg * 64 + mr], b1 = g_bias[rg * 64 + mr + 8];

    if (rg >= 2) {
        const int db = (rg - 2) * 4 + mg;
#pragma unroll
        for (int jg = 0; jg < 4; jg++) {
            int nb0 = 2 * jg, nb1 = 2 * jg + 1;
            uint4 v;
            v.x = bpack(fc[nb0][0] + b0, fc[nb0][1] + b0);
            v.y = bpack(fc[nb1][0] + b0, fc[nb1][1] + b0);
            v.z = bpack(fc[nb0][2] + b1, fc[nb0][3] + b1);
            v.w = bpack(fc[nb1][2] + b1, fc[nb1][3] + b1);
            int kb = blockIdx.x * 8 + nh * 4 + jg;
            g_Vf[(((size_t)b * 32 + db) * 256 + kb) * 32 + lane] = v;
        }
    } else {
        __syncthreads();
        __nv_bfloat16* st = (__nv_bfloat16*)ps;
#pragma unroll
        for (int nb = 0; nb < 8; nb++) {
            int nl = nh * 64 + nb * 8 + (lane & 3) * 2;
            st[nl * 72 + mr]           = __float2bfloat16(fc[nb][0] + b0);
            st[(nl + 1) * 72 + mr]     = __float2bfloat16(fc[nb][1] + b0);
            st[nl * 72 + mr + 8]       = __float2bfloat16(fc[nb][2] + b1);
            st[(nl + 1) * 72 + mr + 8] = __float2bfloat16(fc[nb][3] + b1);
        }
        __syncthreads();
        const int jl = wid * 16 + (lane >> 2);
        const int gb = blockIdx.x * 8 + wid;
#pragma unroll
        for (int ks = 0; ks < 4; ks++) {
            int m = ks * 16 + 2 * (lane & 3);
            uint32_t q00 = *(uint32_t*)&st[jl * 72 + m];
            uint32_t q01 = *(uint32_t*)&st[jl * 72 + m + 8];
            uint32_t q10 = *(uint32_t*)&st[(jl + 8) * 72 + m];
            uint32_t q11 = *(uint32_t*)&st[(jl + 8) * 72 + m + 8];
            size_t fi = (((size_t)b * 256 + gb) * 4 + ks) * 32 + lane;
            if (rg == 0)
                g_Qf[fi] = make_uint4(q00, q10, q01, q11);
            else
                g_Kf[fi] = make_uint4(q00, q01, q10, q11);
        }
    }
}

// =================================================================
// Kernel 2: flash attention. Frag-packed tiles staged via cp.async
// (double-buffered) and consumed with LDS.128. P built in registers.
// CTA = 128 thr (4 warps), 64 q x 128 d. smem = 2 x 24 KB.
// =================================================================
#define KBUF_U4 512          // 4 jb x 4 ks x 32 lanes
#define VBUF_U4 1024         // 8 db x 4 ks x 32 lanes
#define BUF_U4  (KBUF_U4 + VBUF_U4)

__global__ __launch_bounds__(128, 2) void attn_mma(
    const float* __restrict__ x, const float* __restrict__ gamma,
    float* __restrict__ out)
{
    __shared__ __align__(16) uint4 sbuf[2 * BUF_U4];   // 49152 B
    const uint32_t smb = smem_u32(sbuf);
    const int tid  = threadIdx.x;
    const int lane = tid & 31, wid = tid >> 5;
    const int b   = blockIdx.z;
    const int db0 = blockIdx.y * 8;
    const int qb  = blockIdx.x * 4 + wid;

    // persistent Q A-fragments
    uint4 q4[4];
#pragma unroll
    for (int ks = 0; ks < 4; ks++)
        q4[ks] = g_Qf[(((size_t)b * 256 + qb) * 4 + ks) * 32 + lane];

    float facc[16][4];
#pragma unroll
    for (int nb = 0; nb < 16; nb++)
#pragma unroll
        for (int e = 0; e < 4; e++) facc[nb][e] = 0.f;
    float lr0 = 0.f, lr1 = 0.f;

    const uint4* Ksrc = &g_Kf[(size_t)b * 256 * 4 * 32];          // + jt*512
    const uint4* Vsrc = &g_Vf[((size_t)b * 32 + db0) * 256 * 32]; // per db: +jt*128

    // ---- prologue: prefetch jt=0 into buffer 0 ----
    {
        uint32_t dst = smb;
#pragma unroll
        for (int t = 0; t < 4; t++) {
            int idx = tid + t * 128;
            cp16(dst + idx * 16, Ksrc + idx);
        }
#pragma unroll
        for (int t = 0; t < 8; t++) {
            int idx = tid + t * 128;
            int db = idx >> 7, r = idx & 127;
            cp16(dst + (KBUF_U4 + idx) * 16, Vsrc + (size_t)db * 256 * 32 + r);
        }
        CP_COMMIT();
    }

    for (int jt = 0; jt < 64; jt++) {
        __syncthreads();   // everyone done computing jt-1 (buffer jt+1 is free)

        // prefetch jt+1 into buffer (jt+1)&1
        if (jt + 1 < 64) {
            uint32_t dst = smb + ((jt + 1) & 1) * BUF_U4 * 16;
            const uint4* ks2 = Ksrc + (size_t)(jt + 1) * 512;
#pragma unroll
            for (int t = 0; t < 4; t++) {
                int idx = tid + t * 128;
                cp16(dst + idx * 16, ks2 + idx);
            }
#pragma unroll
            for (int t = 0; t < 8; t++) {
                int idx = tid + t * 128;
                int db = idx >> 7, r = idx & 127;
                cp16(dst + (KBUF_U4 + idx) * 16,
                     Vsrc + (size_t)db * 256 * 32 + (size_t)(jt + 1) * 128 + r);
            }
        }
        CP_COMMIT();
        CP_WAIT1();        // jt's tile has landed (jt+1 group may be in flight)
        __syncthreads();

        const uint4* kb = sbuf + (jt & 1) * BUF_U4;
        const uint4* vb = kb + KBUF_U4;

        // ---- scores + exp, one 16-j block at a time (register P) ----
        uint32_t pf[4][4];
#pragma unroll
        for (int jbi = 0; jbi < 4; jbi++) {
            float s0[4] = {0.f, 0.f, 0.f, 0.f};
            float s1[4] = {0.f, 0.f, 0.f, 0.f};
#pragma unroll
            for (int ks = 0; ks < 4; ks++) {
                uint4 kf = kb[(jbi * 4 + ks) * 32 + lane];
                mma16816(s0, (const uint32_t*)&q4[ks], kf.x, kf.y);
                mma16816(s1, (const uint32_t*)&q4[ks], kf.z, kf.w);
            }
            float e0 = __expf(s0[0]), e1 = __expf(s0[1]);
            float e2 = __expf(s0[2]), e3 = __expf(s0[3]);
            float f0 = __expf(s1[0]), f1 = __expf(s1[1]);
            float f2 = __expf(s1[2]), f3 = __expf(s1[3]);
            lr0 += (e0 + e1) + (f0 + f1);
            lr1 += (e2 + e3) + (f2 + f3);
            pf[jbi][0] = bpack(e0, e1);   // (q,   j-lo)
            pf[jbi][1] = bpack(e2, e3);   // (q+8, j-lo)
            pf[jbi][2] = bpack(f0, f1);   // (q,   j-hi)
            pf[jbi][3] = bpack(f2, f3);   // (q+8, j-hi)
        }

        // ---- PV: feat[16q x 128d] += P * V ----
#pragma unroll
        for (int ks = 0; ks < 4; ks++)
#pragma unroll
            for (int nb2 = 0; nb2 < 8; nb2++) {
                uint4 vf = vb[(nb2 * 4 + ks) * 32 + lane];
                mma16816(facc[2 * nb2],     pf[ks], vf.x, vf.y);
                mma16816(facc[2 * nb2 + 1], pf[ks], vf.z, vf.w);
            }
    }

    // ---- row-sum reduce over the 4 lanes of each row group ----
    lr0 += __shfl_xor_sync(0xffffffffu, lr0, 1);
    lr0 += __shfl_xor_sync(0xffffffffu, lr0, 2);
    lr1 += __shfl_xor_sync(0xffffffffu, lr1, 1);
    lr1 += __shfl_xor_sync(0xffffffffu, lr1, 2);

    const float g = gamma[0];
    const float sc0 = g / lr0, sc1 = g / lr1;
    const int q0 = blockIdx.x * 64 + wid * 16 + (lane >> 2);
    const int d0 = blockIdx.y * 128;

#pragma unroll
    for (int nb = 0; nb < 16; nb++) {
        int d = d0 + nb * 8 + 2 * (lane & 3);
        size_t ga = (size_t)(b * CH + d) * NPIX + q0;
        out[ga]            = facc[nb][0] * sc0 + x[ga];
        out[ga + NPIX]     = facc[nb][1] * sc0 + x[ga + NPIX];
        out[ga + 8]        = facc[nb][2] * sc1 + x[ga + 8];
        out[ga + NPIX + 8] = facc[nb][3] * sc1 + x[ga + NPIX + 8];
    }
}

// =================================================================
extern "C" void kernel_launch(void* const* d_in, const int* in_sizes, int n_in,
                              void* d_out, int out_size)
{
    const float* x     = (const float*)d_in[0];
    const float* Wq    = (const float*)d_in[1];
    const float* bq    = (const float*)d_in[2];
    const float* Wk    = (const float*)d_in[3];
    const float* bk    = (const float*)d_in[4];
    const float* Wv    = (const float*)d_in[5];
    const float* bv    = (const float*)d_in[6];
    const float* gamma = (const float*)d_in[7];
    float* out = (float*)d_out;

    conv_x_kernel<<<(BATCH * CH * NPIX) / (256 * 8), 256>>>(x);
    conv_w_kernel<<<160, 256>>>(Wq, bq, Wk, bk, Wv, bv);
    proj_mma_kernel<<<dim3(NPIX / 128, 10, BATCH), 256>>>();
    attn_mma<<<dim3(NPIX / 64, 4, BATCH), 128>>>(x, gamma, out);
}